// round 4
// baseline (speedup 1.0000x reference)
#include <cuda_runtime.h>
#include <math.h>
#include <stdint.h>

// ---------------- problem constants ----------------
#define TOK     18432          // 32 * 576 tokens (b*t, h*w)
#define CTXTOK  2464           // 32 * 77 context tokens
#define DIMC    512
#define NHEAD   8
#define DH      64
#define FFI     1365           // FF inner
#define FF2I    2730           // 2*FFI
#define FFIP    1368           // FF inner padded to /8 (aligned rows for GEMM A)

// ---------------- scratch (device globals; no allocs allowed) ----------------
__device__ float g_x  [TOK * DIMC];
__device__ float g_ln [TOK * DIMC];
__device__ float g_q  [TOK * DIMC];
__device__ float g_k  [TOK * DIMC];
__device__ float g_v  [TOK * DIMC];
__device__ float g_qt [TOK * DIMC];
__device__ float g_xt [TOK * DIMC];
__device__ float g_kv [TOK * FFIP];
__device__ float g_ff [TOK * FF2I];

// ---------------- LayerNorm over last dim (512), 128 threads/row ----------------
__global__ void ln_kernel(const float* __restrict__ x, const float* __restrict__ g,
                          const float* __restrict__ beta, float* __restrict__ y)
{
    __shared__ float sh[8];
    size_t row = blockIdx.x;
    float4 v = reinterpret_cast<const float4*>(x + row * DIMC)[threadIdx.x];
    float s = v.x + v.y + v.z + v.w;
    #pragma unroll
    for (int o = 16; o; o >>= 1) s += __shfl_xor_sync(0xffffffffu, s, o);
    if ((threadIdx.x & 31) == 0) sh[threadIdx.x >> 5] = s;
    __syncthreads();
    float mu = (sh[0] + sh[1] + sh[2] + sh[3]) * (1.0f / 512.0f);
    float dx = v.x - mu, dy = v.y - mu, dz = v.z - mu, dw = v.w - mu;
    float ss = dx * dx + dy * dy + dz * dz + dw * dw;
    #pragma unroll
    for (int o = 16; o; o >>= 1) ss += __shfl_xor_sync(0xffffffffu, ss, o);
    if ((threadIdx.x & 31) == 0) sh[4 + (threadIdx.x >> 5)] = ss;
    __syncthreads();
    float var = (sh[4] + sh[5] + sh[6] + sh[7]) * (1.0f / 512.0f);
    float inv = rsqrtf(var + 1e-5f);
    float4 gg = reinterpret_cast<const float4*>(g)[threadIdx.x];
    float4 o4;
    o4.x = dx * inv * gg.x;
    o4.y = dy * inv * gg.y;
    o4.z = dz * inv * gg.z;
    o4.w = dw * inv * gg.w;
    if (beta) {
        float4 bb = reinterpret_cast<const float4*>(beta)[threadIdx.x];
        o4.x += bb.x; o4.y += bb.y; o4.z += bb.z; o4.w += bb.w;
    }
    reinterpret_cast<float4*>(y + row * DIMC)[threadIdx.x] = o4;
}

// ---------------- tf32 helpers ----------------
__device__ __forceinline__ uint32_t cvt_tf32(float x)
{
    uint32_t r;
    asm("cvt.rna.tf32.f32 %0, %1;" : "=r"(r) : "f"(x));
    return r;
}

__device__ __forceinline__ void mma_tf32(float* c, const uint32_t* a, const uint32_t* b)
{
    asm volatile(
        "mma.sync.aligned.m16n8k8.row.col.f32.tf32.tf32.f32 "
        "{%0,%1,%2,%3}, {%4,%5,%6,%7}, {%8,%9}, {%0,%1,%2,%3};"
        : "+f"(c[0]), "+f"(c[1]), "+f"(c[2]), "+f"(c[3])
        : "r"(a[0]), "r"(a[1]), "r"(a[2]), "r"(a[3]), "r"(b[0]), "r"(b[1]));
}

// ---------------- tensor-core GEMM: C[M,N] = A[M,K] @ B[K,N] (+R) ------------------
// 128x128x16 block tile, 8 warps (2x4), 64x32 warp tile, tf32 mma m16n8k8.
// 2-stage smem double buffer, register LDG prefetch, ONE barrier per k-step.
#define LDA 136
__global__ __launch_bounds__(256, 2) void sgemm_tf32(const float* __restrict__ A, int lda,
                                                     const float* __restrict__ B, int ldb,
                                                     const float* __restrict__ R,
                                                     float* __restrict__ C,
                                                     int M, int N, int K)
{
    __shared__ __align__(16) float As[2][16 * LDA];
    __shared__ __align__(16) float Bs[2][16 * LDA];
    int tid = threadIdx.x;
    int lane = tid & 31;
    int warp = tid >> 5;
    int wm = (warp >> 2) * 64;
    int wn = (warp & 3) * 32;
    int gl = lane >> 2, ql = lane & 3;
    int bm = blockIdx.y * 128, bn = blockIdx.x * 128;
    bool avec = (lda & 3) == 0;
    bool bvec = (ldb & 3) == 0;

    // per-thread staging coordinates (i = 0,1 covers the 128x16 tile)
    int mA[2], kqA[2], kB[2], nqB[2];
    #pragma unroll
    for (int i = 0; i < 2; i++) {
        int f = tid + 256 * i;
        mA[i] = (f & 31) + ((f >> 7) << 5);   // 0..127
        kqA[i] = (f >> 5) & 3;                // k-quad 0..3
        kB[i] = f >> 5;                       // 0..15
        nqB[i] = f & 31;                      // n-quad 0..31
    }

    float acc[4][4][4];
    #pragma unroll
    for (int i = 0; i < 4; i++)
        #pragma unroll
        for (int j = 0; j < 4; j++)
            #pragma unroll
            for (int r = 0; r < 4; r++) acc[i][j][r] = 0.0f;

    uint32_t rA[2][4], rB[2][4];

    auto ldg_stage = [&](int kb) {
        #pragma unroll
        for (int i = 0; i < 2; i++) {
            int m = bm + mA[i];
            int k0 = kb + kqA[i] * 4;
            float4 v = make_float4(0.f, 0.f, 0.f, 0.f);
            if (m < M) {
                const float* p = A + (size_t)m * lda + k0;
                if (avec && k0 + 3 < K) v = *(const float4*)p;
                else {
                    if (k0 + 0 < K) v.x = p[0];
                    if (k0 + 1 < K) v.y = p[1];
                    if (k0 + 2 < K) v.z = p[2];
                    if (k0 + 3 < K) v.w = p[3];
                }
            }
            rA[i][0] = cvt_tf32(v.x); rA[i][1] = cvt_tf32(v.y);
            rA[i][2] = cvt_tf32(v.z); rA[i][3] = cvt_tf32(v.w);
        }
        #pragma unroll
        for (int i = 0; i < 2; i++) {
            int k = kb + kB[i];
            int n0 = bn + nqB[i] * 4;
            float4 v = make_float4(0.f, 0.f, 0.f, 0.f);
            if (k < K) {
                const float* p = B + (size_t)k * ldb + n0;
                if (bvec && n0 + 3 < N) v = *(const float4*)p;
                else {
                    if (n0 + 0 < N) v.x = p[0];
                    if (n0 + 1 < N) v.y = p[1];
                    if (n0 + 2 < N) v.z = p[2];
                    if (n0 + 3 < N) v.w = p[3];
                }
            }
            rB[i][0] = cvt_tf32(v.x); rB[i][1] = cvt_tf32(v.y);
            rB[i][2] = cvt_tf32(v.z); rB[i][3] = cvt_tf32(v.w);
        }
    };

    auto sts_stage = [&](int buf) {
        uint32_t* Asu = (uint32_t*)As[buf];
        uint32_t* Bsu = (uint32_t*)Bs[buf];
        #pragma unroll
        for (int i = 0; i < 2; i++) {
            #pragma unroll
            for (int j = 0; j < 4; j++)
                Asu[(kqA[i] * 4 + j) * LDA + mA[i]] = rA[i][j];   // A transposed
        }
        #pragma unroll
        for (int i = 0; i < 2; i++) {
            uint4* dst = (uint4*)&Bsu[kB[i] * LDA + nqB[i] * 4];
            *dst = make_uint4(rB[i][0], rB[i][1], rB[i][2], rB[i][3]);
        }
    };

    auto compute = [&](int buf) {
        const uint32_t* Asu = (const uint32_t*)As[buf];
        const uint32_t* Bsu = (const uint32_t*)Bs[buf];
        #pragma unroll
        for (int kt = 0; kt < 2; kt++) {
            int k0 = kt * 8;
            uint32_t a[4][4], b[4][2];
            #pragma unroll
            for (int mt = 0; mt < 4; mt++) {
                int m0 = wm + mt * 16 + gl;
                a[mt][0] = Asu[(k0 + ql) * LDA + m0];
                a[mt][1] = Asu[(k0 + ql) * LDA + m0 + 8];
                a[mt][2] = Asu[(k0 + 4 + ql) * LDA + m0];
                a[mt][3] = Asu[(k0 + 4 + ql) * LDA + m0 + 8];
            }
            #pragma unroll
            for (int nt = 0; nt < 4; nt++) {
                int n0 = wn + nt * 8 + gl;
                b[nt][0] = Bsu[(k0 + ql) * LDA + n0];
                b[nt][1] = Bsu[(k0 + 4 + ql) * LDA + n0];
            }
            #pragma unroll
            for (int mt = 0; mt < 4; mt++)
                #pragma unroll
                for (int nt = 0; nt < 4; nt++)
                    mma_tf32(acc[mt][nt], a[mt], b[nt]);
        }
    };

    ldg_stage(0);
    sts_stage(0);
    __syncthreads();
    int buf = 0;
    for (int kb = 0; kb < K; kb += 16) {
        bool more = kb + 16 < K;
        if (more) ldg_stage(kb + 16);
        compute(buf);
        if (more) {
            sts_stage(buf ^ 1);      // other buffer: no hazard with readers of buf
            __syncthreads();
            buf ^= 1;
        }
    }

    // epilogue
    #pragma unroll
    for (int mt = 0; mt < 4; mt++) {
        int r0 = bm + wm + mt * 16 + gl;
        #pragma unroll
        for (int nt = 0; nt < 4; nt++) {
            int c0 = bn + wn + nt * 8 + ql * 2;
            #pragma unroll
            for (int h = 0; h < 2; h++) {          // h=0: rows r0, h=1: r0+8
                int rr = r0 + h * 8;
                if (rr >= M) continue;
                #pragma unroll
                for (int j = 0; j < 2; j++) {
                    int cc = c0 + j;
                    if (cc >= N) continue;
                    size_t idx = (size_t)rr * N + cc;
                    float val = acc[mt][nt][h * 2 + j];
                    if (R) val += R[idx];
                    C[idx] = val;
                }
            }
        }
    }
}

// ---------------- pack token-major -> [BH, N, 64] with optional l2norm*scale*mult ----
__global__ void pack_kernel(const float* __restrict__ src, int stride, int off,
                            float* __restrict__ dst, const float* __restrict__ scale,
                            float mult, int srcN, int dstN, int dstPos)
{
    int m = blockIdx.x;
    int h = threadIdx.y, lane = threadIdx.x;
    int b = m / srcN, i = m % srcN;
    size_t s = (size_t)m * stride + off + h * 64;
    float x0 = src[s + lane], x1 = src[s + 32 + lane];
    float f0 = mult, f1 = mult;
    if (scale) {
        float ss = x0 * x0 + x1 * x1;
        #pragma unroll
        for (int o = 16; o; o >>= 1) ss += __shfl_xor_sync(0xffffffffu, ss, o);
        float inv = 1.0f / fmaxf(sqrtf(ss), 1e-12f);
        f0 = inv * scale[lane] * mult;
        f1 = inv * scale[lane + 32] * mult;
    }
    size_t d = ((size_t)(b * NHEAD + h) * dstN + dstPos + i) * 64;
    dst[d + lane]      = x0 * f0;
    dst[d + 32 + lane] = x1 * f1;
}

// ---------------- fill null-KV tokens (cross-attn) ----------------------------------
__global__ void nullkv_kernel(const float* __restrict__ nkv, const float* __restrict__ ks,
                              float* __restrict__ Kd, float* __restrict__ Vd, int NK)
{
    int b = blockIdx.x; int h = threadIdx.y; int lane = threadIdx.x;
    for (int p = 0; p < 2; p++) {
        const float* nk = nkv + ((size_t)h * 4 + 2 * p) * 64;
        const float* nv = nk + 64;
        float k0 = nk[lane], k1 = nk[lane + 32];
        float ss = k0 * k0 + k1 * k1;
        #pragma unroll
        for (int o = 16; o; o >>= 1) ss += __shfl_xor_sync(0xffffffffu, ss, o);
        float inv = 1.0f / fmaxf(sqrtf(ss), 1e-12f);
        size_t base = ((size_t)(b * NHEAD + h) * NK + p) * 64;
        Kd[base + lane]      = k0 * inv * ks[lane];
        Kd[base + 32 + lane] = k1 * inv * ks[lane + 32];
        Vd[base + lane]      = nv[lane];
        Vd[base + 32 + lane] = nv[lane + 32];
    }
}

// ---------------- attention: warp per query, online softmax -------------------------
__global__ __launch_bounds__(256) void attn_kernel(const float* __restrict__ Q,
                                                   const float* __restrict__ K,
                                                   const float* __restrict__ V,
                                                   float* __restrict__ O,
                                                   int NQ, int NK, int causal)
{
    __shared__ float Ks[32][64];
    __shared__ float Vs[32][64];
    int bh = blockIdx.y;
    int tid = threadIdx.x;
    int w = tid >> 5, lane = tid & 31;
    int qi = blockIdx.x * 8 + w;
    bool qv = qi < NQ;
    float qa = 0.f, qb = 0.f;
    if (qv) {
        size_t qoff = ((size_t)bh * NQ + qi) * 64;
        qa = Q[qoff + lane];
        qb = Q[qoff + 32 + lane];
    }
    float m = -1e30f, l = 0.f, acc0 = 0.f, acc1 = 0.f;
    float slope = exp2f(-(float)((bh & 7) + 1));

    for (int kt = 0; kt < NK; kt += 32) {
        for (int f = tid; f < 2048; f += 256) {
            int j = f >> 6, d = f & 63;
            int jg = kt + j;
            bool ok = jg < NK;
            size_t off = ((size_t)bh * NK + (ok ? jg : 0)) * 64 + d;
            Ks[j][d] = ok ? K[off] : 0.0f;
            Vs[j][d] = ok ? V[off] : 0.0f;
        }
        __syncthreads();
        if (qv) {
            int jmax = NK - kt; if (jmax > 32) jmax = 32;
            for (int j = 0; j < jmax; j++) {
                int jg = kt + j;
                if (causal && jg > qi) break;
                float s = qa * Ks[j][lane] + qb * Ks[j][lane + 32];
                #pragma unroll
                for (int o = 16; o; o >>= 1) s += __shfl_xor_sync(0xffffffffu, s, o);
                if (causal) s -= slope * (float)(qi - jg);
                float mn = fmaxf(m, s);
                float corr = __expf(m - mn);
                float p = __expf(s - mn);
                l    = l * corr + p;
                acc0 = acc0 * corr + p * Vs[j][lane];
                acc1 = acc1 * corr + p * Vs[j][lane + 32];
                m = mn;
            }
        }
        __syncthreads();
    }
    if (qv) {
        float inv = 1.0f / l;
        int b = bh >> 3, hh = bh & 7;
        size_t o = ((size_t)b * NQ + qi) * DIMC + hh * 64;
        O[o + lane]      = acc0 * inv;
        O[o + 32 + lane] = acc1 * inv;
    }
}

// ---------------- temporal transpose (b,t,s,c) <-> (b,s,t,c), c=512 ------------------
__global__ void transpose_kernel(const float* __restrict__ src, float* __restrict__ dst,
                                 int dir)
{
    int mIdx = blockIdx.x;
    int b = mIdx / (16 * 576);
    int r = mIdx % (16 * 576);
    int t = r / 576, s = r % 576;
    size_t ia = ((size_t)(b * 16 + t) * 576 + s) * DIMC;
    size_t ib = ((size_t)(b * 576 + s) * 16 + t) * DIMC;
    const float4* in;
    float4* out;
    if (dir == 0) { in = (const float4*)(src + ia); out = (float4*)(dst + ib); }
    else          { in = (const float4*)(src + ib); out = (float4*)(dst + ia); }
    out[threadIdx.x] = in[threadIdx.x];
}

// ---------------- GEGLU: out = u * gelu_exact(gate), out row stride FFIP -------------
__global__ void geglu_kernel(const float* __restrict__ ff, float* __restrict__ out)
{
    int m = blockIdx.x;
    const float* r = ff + (size_t)m * FF2I;
    float* o = out + (size_t)m * FFIP;
    for (int c = threadIdx.x; c < FFI; c += 256) {
        float u = r[c], g = r[FFI + c];
        o[c] = u * g * normcdff(g);
    }
}

// ---------------- host orchestration -------------------------------------------------
extern "C" void kernel_launch(void* const* d_in, const int* in_sizes, int n_in,
                              void* d_out, int out_size)
{
    (void)in_sizes; (void)n_in; (void)out_size;
    const float* x      = (const float*)d_in[0];
    const float* ctx    = (const float*)d_in[1];
    const float* sp_g   = (const float*)d_in[2];
    const float* sp_wq  = (const float*)d_in[3];
    const float* sp_wkv = (const float*)d_in[4];
    const float* sp_qs  = (const float*)d_in[5];
    const float* sp_ks  = (const float*)d_in[6];
    const float* sp_wo  = (const float*)d_in[7];
    const float* ca_g   = (const float*)d_in[8];
    const float* ca_cg  = (const float*)d_in[9];
    const float* ca_wq  = (const float*)d_in[10];
    const float* ca_wkv = (const float*)d_in[11];
    const float* ca_qs  = (const float*)d_in[12];
    const float* ca_ks  = (const float*)d_in[13];
    const float* ca_wo  = (const float*)d_in[14];
    const float* ca_nul = (const float*)d_in[15];
    const float* tp_g   = (const float*)d_in[16];
    const float* tp_wq  = (const float*)d_in[17];
    const float* tp_wkv = (const float*)d_in[18];
    const float* tp_qs  = (const float*)d_in[19];
    const float* tp_ks  = (const float*)d_in[20];
    const float* tp_wo  = (const float*)d_in[21];
    const float* ff_g   = (const float*)d_in[22];
    const float* ff_b   = (const float*)d_in[23];
    const float* ff_w1  = (const float*)d_in[24];
    const float* ff_w2  = (const float*)d_in[25];
    const float* out_g  = (const float*)d_in[26];
    float* out = (float*)d_out;

    float *px, *pln, *pq, *pk, *pv, *pqt, *pxt, *pkv, *pff;
    cudaGetSymbolAddress((void**)&px,  g_x);
    cudaGetSymbolAddress((void**)&pln, g_ln);
    cudaGetSymbolAddress((void**)&pq,  g_q);
    cudaGetSymbolAddress((void**)&pk,  g_k);
    cudaGetSymbolAddress((void**)&pv,  g_v);
    cudaGetSymbolAddress((void**)&pqt, g_qt);
    cudaGetSymbolAddress((void**)&pxt, g_xt);
    cudaGetSymbolAddress((void**)&pkv, g_kv);
    cudaGetSymbolAddress((void**)&pff, g_ff);

    dim3 bwh(32, 8);

    // ---- Phase A: spatial self-attention ----
    ln_kernel<<<TOK, 128>>>(x, sp_g, nullptr, pln);
    sgemm_tf32<<<dim3(4, 144), 256>>>(pln, 512, sp_wq, 512,  nullptr, pqt, TOK, 512, 512);
    sgemm_tf32<<<dim3(8, 144), 256>>>(pln, 512, sp_wkv, 1024, nullptr, pkv, TOK, 1024, 512);
    pack_kernel<<<TOK, bwh>>>(pqt, 512, 0,    pq, sp_qs,   8.0f, 576, 576, 0);
    pack_kernel<<<TOK, bwh>>>(pkv, 1024, 0,   pk, sp_ks,   1.0f, 576, 576, 0);
    pack_kernel<<<TOK, bwh>>>(pkv, 1024, 512, pv, nullptr, 1.0f, 576, 576, 0);
    attn_kernel<<<dim3(72, 256), 256>>>(pq, pk, pv, pln, 576, 576, 0);
    sgemm_tf32<<<dim3(4, 144), 256>>>(pln, 512, sp_wo, 512, x, px, TOK, 512, 512);

    // ---- Phase B: spatial cross-attention (null kv) ----
    ln_kernel<<<TOK, 128>>>(px, ca_g, nullptr, pln);
    ln_kernel<<<CTXTOK, 128>>>(ctx, ca_cg, nullptr, pxt);
    sgemm_tf32<<<dim3(4, 144), 256>>>(pln, 512, ca_wq, 512,  nullptr, pqt, TOK, 512, 512);
    sgemm_tf32<<<dim3(8, 20),  256>>>(pxt, 512, ca_wkv, 1024, nullptr, pkv, CTXTOK, 1024, 512);
    nullkv_kernel<<<32, bwh>>>(ca_nul, ca_ks, pk, pv, 79);
    pack_kernel<<<TOK, bwh>>>(pqt, 512, 0,       pq, ca_qs,   8.0f, 576, 576, 0);
    pack_kernel<<<CTXTOK, bwh>>>(pkv, 1024, 0,   pk, ca_ks,   1.0f, 77, 79, 2);
    pack_kernel<<<CTXTOK, bwh>>>(pkv, 1024, 512, pv, nullptr, 1.0f, 77, 79, 2);
    attn_kernel<<<dim3(72, 256), 256>>>(pq, pk, pv, pln, 576, 79, 0);
    sgemm_tf32<<<dim3(4, 144), 256>>>(pln, 512, ca_wo, 512, px, px, TOK, 512, 512);

    // ---- Phase C: temporal causal self-attention with ALiBi ----
    transpose_kernel<<<TOK, 128>>>(px, pxt, 0);
    ln_kernel<<<TOK, 128>>>(pxt, tp_g, nullptr, pln);
    sgemm_tf32<<<dim3(4, 144), 256>>>(pln, 512, tp_wq, 512,  nullptr, pqt, TOK, 512, 512);
    sgemm_tf32<<<dim3(8, 144), 256>>>(pln, 512, tp_wkv, 1024, nullptr, pkv, TOK, 1024, 512);
    pack_kernel<<<TOK, bwh>>>(pqt, 512, 0,    pq, tp_qs,   8.0f, 16, 16, 0);
    pack_kernel<<<TOK, bwh>>>(pkv, 1024, 0,   pk, tp_ks,   1.0f, 16, 16, 0);
    pack_kernel<<<TOK, bwh>>>(pkv, 1024, 512, pv, nullptr, 1.0f, 16, 16, 0);
    attn_kernel<<<dim3(2, 9216), 256>>>(pq, pk, pv, pln, 16, 16, 1);
    sgemm_tf32<<<dim3(4, 144), 256>>>(pln, 512, tp_wo, 512, pxt, pxt, TOK, 512, 512);
    transpose_kernel<<<TOK, 128>>>(pxt, px, 1);

    // ---- Phase D: GEGLU FF + final LN ----
    ln_kernel<<<TOK, 128>>>(px, ff_g, ff_b, pln);
    sgemm_tf32<<<dim3(22, 144), 256>>>(pln, 512, ff_w1, FF2I, nullptr, pff, TOK, FF2I, 512);
    geglu_kernel<<<TOK, 256>>>(pff, pkv);
    sgemm_tf32<<<dim3(4, 144), 256>>>(pkv, FFIP, ff_w2, 512, px, px, TOK, 512, FFI);
    ln_kernel<<<TOK, 128>>>(px, out_g, nullptr, out);
}

// round 5
// speedup vs baseline: 2.4098x; 2.4098x over previous
#include <cuda_runtime.h>
#include <cuda_bf16.h>
#include <math.h>
#include <stdint.h>

// ---------------- problem constants ----------------
#define TOK     18432          // 32 * 576 tokens (b*t, h*w)
#define CTXTOK  2464           // 32 * 77 context tokens
#define DIMC    512
#define NHEAD   8
#define DH      64
#define FFI     1365           // FF inner
#define FF2I    2730           // 2*FFI
#define FFIP    1368           // FF inner padded to /8 (aligned rows for GEMM A)

// ---------------- scratch (device globals; no allocs allowed) ----------------
__device__ float g_x  [TOK * DIMC];
__device__ float g_ln [TOK * DIMC];
__device__ float g_q  [TOK * DIMC];
__device__ float g_k  [TOK * DIMC];
__device__ float g_v  [TOK * DIMC];
__device__ float g_qt [TOK * DIMC];
__device__ float g_xt [TOK * DIMC];
__device__ float g_kv [TOK * FFIP];
__device__ float g_ff [TOK * FF2I];

// ---------------- LayerNorm over last dim (512), 128 threads/row ----------------
__global__ void ln_kernel(const float* __restrict__ x, const float* __restrict__ g,
                          const float* __restrict__ beta, float* __restrict__ y)
{
    __shared__ float sh[8];
    size_t row = blockIdx.x;
    float4 v = reinterpret_cast<const float4*>(x + row * DIMC)[threadIdx.x];
    float s = v.x + v.y + v.z + v.w;
    #pragma unroll
    for (int o = 16; o; o >>= 1) s += __shfl_xor_sync(0xffffffffu, s, o);
    if ((threadIdx.x & 31) == 0) sh[threadIdx.x >> 5] = s;
    __syncthreads();
    float mu = (sh[0] + sh[1] + sh[2] + sh[3]) * (1.0f / 512.0f);
    float dx = v.x - mu, dy = v.y - mu, dz = v.z - mu, dw = v.w - mu;
    float ss = dx * dx + dy * dy + dz * dz + dw * dw;
    #pragma unroll
    for (int o = 16; o; o >>= 1) ss += __shfl_xor_sync(0xffffffffu, ss, o);
    if ((threadIdx.x & 31) == 0) sh[4 + (threadIdx.x >> 5)] = ss;
    __syncthreads();
    float var = (sh[4] + sh[5] + sh[6] + sh[7]) * (1.0f / 512.0f);
    float inv = rsqrtf(var + 1e-5f);
    float4 gg = reinterpret_cast<const float4*>(g)[threadIdx.x];
    float4 o4;
    o4.x = dx * inv * gg.x;
    o4.y = dy * inv * gg.y;
    o4.z = dz * inv * gg.z;
    o4.w = dw * inv * gg.w;
    if (beta) {
        float4 bb = reinterpret_cast<const float4*>(beta)[threadIdx.x];
        o4.x += bb.x; o4.y += bb.y; o4.z += bb.z; o4.w += bb.w;
    }
    reinterpret_cast<float4*>(y + row * DIMC)[threadIdx.x] = o4;
}

// ---------------- mma helpers ----------------
__device__ __forceinline__ uint32_t cvt_tf32(float x)
{
    uint32_t r;
    asm("cvt.rna.tf32.f32 %0, %1;" : "=r"(r) : "f"(x));
    return r;
}

__device__ __forceinline__ void mma_tf32(float* c, const uint32_t* a, const uint32_t* b)
{
    asm volatile(
        "mma.sync.aligned.m16n8k8.row.col.f32.tf32.tf32.f32 "
        "{%0,%1,%2,%3}, {%4,%5,%6,%7}, {%8,%9}, {%0,%1,%2,%3};"
        : "+f"(c[0]), "+f"(c[1]), "+f"(c[2]), "+f"(c[3])
        : "r"(a[0]), "r"(a[1]), "r"(a[2]), "r"(a[3]), "r"(b[0]), "r"(b[1]));
}

__device__ __forceinline__ void mma_bf16(float* c, const uint32_t* a, uint32_t b0, uint32_t b1)
{
    asm volatile(
        "mma.sync.aligned.m16n8k16.row.col.f32.bf16.bf16.f32 "
        "{%0,%1,%2,%3}, {%4,%5,%6,%7}, {%8,%9}, {%0,%1,%2,%3};"
        : "+f"(c[0]), "+f"(c[1]), "+f"(c[2]), "+f"(c[3])
        : "r"(a[0]), "r"(a[1]), "r"(a[2]), "r"(a[3]), "r"(b0), "r"(b1));
}

__device__ __forceinline__ uint32_t pack_bf16(float lo, float hi)
{
    uint32_t r;
    asm("cvt.rn.bf16x2.f32 %0, %1, %2;" : "=r"(r) : "f"(hi), "f"(lo));
    return r;
}

// ---------------- tensor-core GEMM: C[M,N] = A[M,K] @ B[K,N] (+R) ------------------
// 128x128x16 block tile, 8 warps (2x4), 64x32 warp tile, tf32 mma m16n8k8.
#define LDA 136
__global__ __launch_bounds__(256, 2) void sgemm_tf32(const float* __restrict__ A, int lda,
                                                     const float* __restrict__ B, int ldb,
                                                     const float* __restrict__ R,
                                                     float* __restrict__ C,
                                                     int M, int N, int K)
{
    __shared__ __align__(16) float As[2][16 * LDA];
    __shared__ __align__(16) float Bs[2][16 * LDA];
    int tid = threadIdx.x;
    int lane = tid & 31;
    int warp = tid >> 5;
    int wm = (warp >> 2) * 64;
    int wn = (warp & 3) * 32;
    int gl = lane >> 2, ql = lane & 3;
    int bm = blockIdx.y * 128, bn = blockIdx.x * 128;
    bool avec = (lda & 3) == 0;
    bool bvec = (ldb & 3) == 0;

    int mA[2], kqA[2], kB[2], nqB[2];
    #pragma unroll
    for (int i = 0; i < 2; i++) {
        int f = tid + 256 * i;
        mA[i] = (f & 31) + ((f >> 7) << 5);
        kqA[i] = (f >> 5) & 3;
        kB[i] = f >> 5;
        nqB[i] = f & 31;
    }

    float acc[4][4][4];
    #pragma unroll
    for (int i = 0; i < 4; i++)
        #pragma unroll
        for (int j = 0; j < 4; j++)
            #pragma unroll
            for (int r = 0; r < 4; r++) acc[i][j][r] = 0.0f;

    uint32_t rA[2][4], rB[2][4];

    auto ldg_stage = [&](int kb) {
        #pragma unroll
        for (int i = 0; i < 2; i++) {
            int m = bm + mA[i];
            int k0 = kb + kqA[i] * 4;
            float4 v = make_float4(0.f, 0.f, 0.f, 0.f);
            if (m < M) {
                const float* p = A + (size_t)m * lda + k0;
                if (avec && k0 + 3 < K) v = *(const float4*)p;
                else {
                    if (k0 + 0 < K) v.x = p[0];
                    if (k0 + 1 < K) v.y = p[1];
                    if (k0 + 2 < K) v.z = p[2];
                    if (k0 + 3 < K) v.w = p[3];
                }
            }
            rA[i][0] = cvt_tf32(v.x); rA[i][1] = cvt_tf32(v.y);
            rA[i][2] = cvt_tf32(v.z); rA[i][3] = cvt_tf32(v.w);
        }
        #pragma unroll
        for (int i = 0; i < 2; i++) {
            int k = kb + kB[i];
            int n0 = bn + nqB[i] * 4;
            float4 v = make_float4(0.f, 0.f, 0.f, 0.f);
            if (k < K) {
                const float* p = B + (size_t)k * ldb + n0;
                if (bvec && n0 + 3 < N) v = *(const float4*)p;
                else {
                    if (n0 + 0 < N) v.x = p[0];
                    if (n0 + 1 < N) v.y = p[1];
                    if (n0 + 2 < N) v.z = p[2];
                    if (n0 + 3 < N) v.w = p[3];
                }
            }
            rB[i][0] = cvt_tf32(v.x); rB[i][1] = cvt_tf32(v.y);
            rB[i][2] = cvt_tf32(v.z); rB[i][3] = cvt_tf32(v.w);
        }
    };

    auto sts_stage = [&](int buf) {
        uint32_t* Asu = (uint32_t*)As[buf];
        uint32_t* Bsu = (uint32_t*)Bs[buf];
        #pragma unroll
        for (int i = 0; i < 2; i++) {
            #pragma unroll
            for (int j = 0; j < 4; j++)
                Asu[(kqA[i] * 4 + j) * LDA + mA[i]] = rA[i][j];
        }
        #pragma unroll
        for (int i = 0; i < 2; i++) {
            uint4* dst = (uint4*)&Bsu[kB[i] * LDA + nqB[i] * 4];
            *dst = make_uint4(rB[i][0], rB[i][1], rB[i][2], rB[i][3]);
        }
    };

    auto compute = [&](int buf) {
        const uint32_t* Asu = (const uint32_t*)As[buf];
        const uint32_t* Bsu = (const uint32_t*)Bs[buf];
        #pragma unroll
        for (int kt = 0; kt < 2; kt++) {
            int k0 = kt * 8;
            uint32_t a[4][4], b[4][2];
            #pragma unroll
            for (int mt = 0; mt < 4; mt++) {
                int m0 = wm + mt * 16 + gl;
                a[mt][0] = Asu[(k0 + ql) * LDA + m0];
                a[mt][1] = Asu[(k0 + ql) * LDA + m0 + 8];
                a[mt][2] = Asu[(k0 + 4 + ql) * LDA + m0];
                a[mt][3] = Asu[(k0 + 4 + ql) * LDA + m0 + 8];
            }
            #pragma unroll
            for (int nt = 0; nt < 4; nt++) {
                int n0 = wn + nt * 8 + gl;
                b[nt][0] = Bsu[(k0 + ql) * LDA + n0];
                b[nt][1] = Bsu[(k0 + 4 + ql) * LDA + n0];
            }
            #pragma unroll
            for (int mt = 0; mt < 4; mt++)
                #pragma unroll
                for (int nt = 0; nt < 4; nt++)
                    mma_tf32(acc[mt][nt], a[mt], b[nt]);
        }
    };

    ldg_stage(0);
    sts_stage(0);
    __syncthreads();
    int buf = 0;
    for (int kb = 0; kb < K; kb += 16) {
        bool more = kb + 16 < K;
        if (more) ldg_stage(kb + 16);
        compute(buf);
        if (more) {
            sts_stage(buf ^ 1);
            __syncthreads();
            buf ^= 1;
        }
    }

    #pragma unroll
    for (int mt = 0; mt < 4; mt++) {
        int r0 = bm + wm + mt * 16 + gl;
        #pragma unroll
        for (int nt = 0; nt < 4; nt++) {
            int c0 = bn + wn + nt * 8 + ql * 2;
            #pragma unroll
            for (int h = 0; h < 2; h++) {
                int rr = r0 + h * 8;
                if (rr >= M) continue;
                #pragma unroll
                for (int j = 0; j < 2; j++) {
                    int cc = c0 + j;
                    if (cc >= N) continue;
                    size_t idx = (size_t)rr * N + cc;
                    float val = acc[mt][nt][h * 2 + j];
                    if (R) val += R[idx];
                    C[idx] = val;
                }
            }
        }
    }
}

// ---------------- tensor-core flash attention (non-causal) --------------------------
// Block: 128 threads / 4 warps = 64 queries of one bh. Tile 32 keys.
// S = Q@K^T via m16n8k8.tf32, online softmax, O += P@V via m16n8k16.bf16.
#define KPITCH 68     // floats per key row in smem (conflict-free b-frags)
#define VPITCH 40     // bf16 per d row in smem (conflict-free b-frags)
__global__ __launch_bounds__(128) void attn_mma_kernel(const float* __restrict__ Q,
                                                       const float* __restrict__ K,
                                                       const float* __restrict__ V,
                                                       float* __restrict__ O,
                                                       int NQ, int NK)
{
    __shared__ __align__(16) uint32_t Ks[32 * KPITCH];
    __shared__ __align__(16) __nv_bfloat16 Vst[64 * VPITCH];
    int tid = threadIdx.x;
    int lane = tid & 31, warp = tid >> 5;
    int gl = lane >> 2, ql = lane & 3;
    int bh = blockIdx.y;
    int q0 = blockIdx.x * 64 + warp * 16;

    // Q fragments (rows q0+gl / q0+gl+8, all 64 dims) — held for the whole kernel
    uint32_t qf[8][4];
    const float* Qb = Q + ((size_t)bh * NQ + q0) * 64;
    #pragma unroll
    for (int kc = 0; kc < 8; kc++) {
        qf[kc][0] = cvt_tf32(Qb[gl * 64 + kc * 8 + ql]);
        qf[kc][1] = cvt_tf32(Qb[(gl + 8) * 64 + kc * 8 + ql]);
        qf[kc][2] = cvt_tf32(Qb[gl * 64 + kc * 8 + ql + 4]);
        qf[kc][3] = cvt_tf32(Qb[(gl + 8) * 64 + kc * 8 + ql + 4]);
    }

    float o[8][4];
    #pragma unroll
    for (int i = 0; i < 8; i++)
        #pragma unroll
        for (int j = 0; j < 4; j++) o[i][j] = 0.0f;
    float m0 = -1e30f, m1 = -1e30f, l0 = 0.0f, l1 = 0.0f;

    for (int kt = 0; kt < NK; kt += 32) {
        // ---- stage K tile (tf32, [key][d] pitch 68) ----
        #pragma unroll
        for (int i = 0; i < 4; i++) {
            int f = tid + i * 128;          // 512 float4 units = 32 keys x 16
            int key = f >> 4;
            int c4 = f & 15;
            int jg = kt + key;
            float4 v = make_float4(0.f, 0.f, 0.f, 0.f);
            if (jg < NK) v = *(const float4*)(K + ((size_t)bh * NK + jg) * 64 + c4 * 4);
            uint4 w = make_uint4(cvt_tf32(v.x), cvt_tf32(v.y), cvt_tf32(v.z), cvt_tf32(v.w));
            *(uint4*)&Ks[key * KPITCH + c4 * 4] = w;
        }
        // ---- stage V^T tile (bf16, [d][key] pitch 40) ----
        {
            int key = tid & 31, dg = tid >> 5;   // dg in 0..3, d = dg*16 .. +15
            int jg = kt + key;
            #pragma unroll
            for (int i = 0; i < 4; i++) {
                int d0 = dg * 16 + i * 4;
                float4 v = make_float4(0.f, 0.f, 0.f, 0.f);
                if (jg < NK) v = *(const float4*)(V + ((size_t)bh * NK + jg) * 64 + d0);
                Vst[(d0 + 0) * VPITCH + key] = __float2bfloat16(v.x);
                Vst[(d0 + 1) * VPITCH + key] = __float2bfloat16(v.y);
                Vst[(d0 + 2) * VPITCH + key] = __float2bfloat16(v.z);
                Vst[(d0 + 3) * VPITCH + key] = __float2bfloat16(v.w);
            }
        }
        __syncthreads();

        // ---- S = Q @ K^T (16 x 32 per warp) ----
        float s[4][4];
        #pragma unroll
        for (int nt = 0; nt < 4; nt++)
            #pragma unroll
            for (int j = 0; j < 4; j++) s[nt][j] = 0.0f;
        #pragma unroll
        for (int kc = 0; kc < 8; kc++) {
            #pragma unroll
            for (int nt = 0; nt < 4; nt++) {
                uint32_t b[2];
                b[0] = Ks[(nt * 8 + gl) * KPITCH + kc * 8 + ql];
                b[1] = Ks[(nt * 8 + gl) * KPITCH + kc * 8 + ql + 4];
                mma_tf32(s[nt], qf[kc], b);
            }
        }

        // ---- mask padded keys (cross-attn last tile) ----
        if (kt + 32 > NK) {
            #pragma unroll
            for (int nt = 0; nt < 4; nt++) {
                int jg = kt + nt * 8 + 2 * ql;
                if (jg >= NK)     { s[nt][0] = -1e30f; s[nt][2] = -1e30f; }
                if (jg + 1 >= NK) { s[nt][1] = -1e30f; s[nt][3] = -1e30f; }
            }
        }

        // ---- online softmax (rows gl and gl+8) ----
        float tm0 = -1e30f, tm1 = -1e30f;
        #pragma unroll
        for (int nt = 0; nt < 4; nt++) {
            tm0 = fmaxf(tm0, fmaxf(s[nt][0], s[nt][1]));
            tm1 = fmaxf(tm1, fmaxf(s[nt][2], s[nt][3]));
        }
        #pragma unroll
        for (int off = 1; off <= 2; off <<= 1) {
            tm0 = fmaxf(tm0, __shfl_xor_sync(0xffffffffu, tm0, off));
            tm1 = fmaxf(tm1, __shfl_xor_sync(0xffffffffu, tm1, off));
        }
        float nm0 = fmaxf(m0, tm0), nm1 = fmaxf(m1, tm1);
        float c0 = __expf(m0 - nm0), c1 = __expf(m1 - nm1);
        float rs0 = 0.0f, rs1 = 0.0f;
        #pragma unroll
        for (int nt = 0; nt < 4; nt++) {
            s[nt][0] = __expf(s[nt][0] - nm0);
            s[nt][1] = __expf(s[nt][1] - nm0);
            s[nt][2] = __expf(s[nt][2] - nm1);
            s[nt][3] = __expf(s[nt][3] - nm1);
            rs0 += s[nt][0] + s[nt][1];
            rs1 += s[nt][2] + s[nt][3];
        }
        #pragma unroll
        for (int off = 1; off <= 2; off <<= 1) {
            rs0 += __shfl_xor_sync(0xffffffffu, rs0, off);
            rs1 += __shfl_xor_sync(0xffffffffu, rs1, off);
        }
        l0 = l0 * c0 + rs0;
        l1 = l1 * c1 + rs1;
        m0 = nm0; m1 = nm1;
        #pragma unroll
        for (int nt = 0; nt < 8; nt++) {
            o[nt][0] *= c0; o[nt][1] *= c0;
            o[nt][2] *= c1; o[nt][3] *= c1;
        }

        // ---- O += P @ V (bf16 m16n8k16; C layout of S == A layout of bf16 mma) ----
        #pragma unroll
        for (int kc = 0; kc < 2; kc++) {
            uint32_t a[4];
            a[0] = pack_bf16(s[2 * kc][0],     s[2 * kc][1]);
            a[1] = pack_bf16(s[2 * kc][2],     s[2 * kc][3]);
            a[2] = pack_bf16(s[2 * kc + 1][0], s[2 * kc + 1][1]);
            a[3] = pack_bf16(s[2 * kc + 1][2], s[2 * kc + 1][3]);
            #pragma unroll
            for (int nt = 0; nt < 8; nt++) {
                const __nv_bfloat16* vp = &Vst[(nt * 8 + gl) * VPITCH + kc * 16 + 2 * ql];
                uint32_t b0 = *(const uint32_t*)vp;
                uint32_t b1 = *(const uint32_t*)(vp + 8);
                mma_bf16(o[nt], a, b0, b1);
            }
        }
        __syncthreads();
    }

    // ---- epilogue: normalize, scatter to token-major [b][q][512] ----
    float inv0 = 1.0f / l0, inv1 = 1.0f / l1;
    int b = bh >> 3, h = bh & 7;
    #pragma unroll
    for (int nt = 0; nt < 8; nt++) {
        int d = h * 64 + nt * 8 + 2 * ql;
        float2 v0 = make_float2(o[nt][0] * inv0, o[nt][1] * inv0);
        float2 v1 = make_float2(o[nt][2] * inv1, o[nt][3] * inv1);
        *(float2*)&O[((size_t)b * NQ + q0 + gl) * DIMC + d] = v0;
        *(float2*)&O[((size_t)b * NQ + q0 + gl + 8) * DIMC + d] = v1;
    }
}

// ---------------- pack token-major -> [BH, N, 64] with optional l2norm*scale*mult ----
__global__ void pack_kernel(const float* __restrict__ src, int stride, int off,
                            float* __restrict__ dst, const float* __restrict__ scale,
                            float mult, int srcN, int dstN, int dstPos)
{
    int m = blockIdx.x;
    int h = threadIdx.y, lane = threadIdx.x;
    int b = m / srcN, i = m % srcN;
    size_t s = (size_t)m * stride + off + h * 64;
    float x0 = src[s + lane], x1 = src[s + 32 + lane];
    float f0 = mult, f1 = mult;
    if (scale) {
        float ss = x0 * x0 + x1 * x1;
        #pragma unroll
        for (int o = 16; o; o >>= 1) ss += __shfl_xor_sync(0xffffffffu, ss, o);
        float inv = 1.0f / fmaxf(sqrtf(ss), 1e-12f);
        f0 = inv * scale[lane] * mult;
        f1 = inv * scale[lane + 32] * mult;
    }
    size_t d = ((size_t)(b * NHEAD + h) * dstN + dstPos + i) * 64;
    dst[d + lane]      = x0 * f0;
    dst[d + 32 + lane] = x1 * f1;
}

// ---------------- fill null-KV tokens (cross-attn) ----------------------------------
__global__ void nullkv_kernel(const float* __restrict__ nkv, const float* __restrict__ ks,
                              float* __restrict__ Kd, float* __restrict__ Vd, int NK)
{
    int b = blockIdx.x; int h = threadIdx.y; int lane = threadIdx.x;
    for (int p = 0; p < 2; p++) {
        const float* nk = nkv + ((size_t)h * 4 + 2 * p) * 64;
        const float* nv = nk + 64;
        float k0 = nk[lane], k1 = nk[lane + 32];
        float ss = k0 * k0 + k1 * k1;
        #pragma unroll
        for (int o = 16; o; o >>= 1) ss += __shfl_xor_sync(0xffffffffu, ss, o);
        float inv = 1.0f / fmaxf(sqrtf(ss), 1e-12f);
        size_t base = ((size_t)(b * NHEAD + h) * NK + p) * 64;
        Kd[base + lane]      = k0 * inv * ks[lane];
        Kd[base + 32 + lane] = k1 * inv * ks[lane + 32];
        Vd[base + lane]      = nv[lane];
        Vd[base + 32 + lane] = nv[lane + 32];
    }
}

// ---------------- scalar attention (temporal: NK=16, causal + ALiBi) ----------------
__global__ __launch_bounds__(256) void attn_kernel(const float* __restrict__ Q,
                                                   const float* __restrict__ K,
                                                   const float* __restrict__ V,
                                                   float* __restrict__ O,
                                                   int NQ, int NK, int causal)
{
    __shared__ float Ks[32][64];
    __shared__ float Vs[32][64];
    int bh = blockIdx.y;
    int tid = threadIdx.x;
    int w = tid >> 5, lane = tid & 31;
    int qi = blockIdx.x * 8 + w;
    bool qv = qi < NQ;
    float qa = 0.f, qb = 0.f;
    if (qv) {
        size_t qoff = ((size_t)bh * NQ + qi) * 64;
        qa = Q[qoff + lane];
        qb = Q[qoff + 32 + lane];
    }
    float m = -1e30f, l = 0.f, acc0 = 0.f, acc1 = 0.f;
    float slope = exp2f(-(float)((bh & 7) + 1));

    for (int kt = 0; kt < NK; kt += 32) {
        for (int f = tid; f < 2048; f += 256) {
            int j = f >> 6, d = f & 63;
            int jg = kt + j;
            bool ok = jg < NK;
            size_t off = ((size_t)bh * NK + (ok ? jg : 0)) * 64 + d;
            Ks[j][d] = ok ? K[off] : 0.0f;
            Vs[j][d] = ok ? V[off] : 0.0f;
        }
        __syncthreads();
        if (qv) {
            int jmax = NK - kt; if (jmax > 32) jmax = 32;
            for (int j = 0; j < jmax; j++) {
                int jg = kt + j;
                if (causal && jg > qi) break;
                float s = qa * Ks[j][lane] + qb * Ks[j][lane + 32];
                #pragma unroll
                for (int o = 16; o; o >>= 1) s += __shfl_xor_sync(0xffffffffu, s, o);
                if (causal) s -= slope * (float)(qi - jg);
                float mn = fmaxf(m, s);
                float corr = __expf(m - mn);
                float p = __expf(s - mn);
                l    = l * corr + p;
                acc0 = acc0 * corr + p * Vs[j][lane];
                acc1 = acc1 * corr + p * Vs[j][lane + 32];
                m = mn;
            }
        }
        __syncthreads();
    }
    if (qv) {
        float inv = 1.0f / l;
        int b = bh >> 3, hh = bh & 7;
        size_t o = ((size_t)b * NQ + qi) * DIMC + hh * 64;
        O[o + lane]      = acc0 * inv;
        O[o + 32 + lane] = acc1 * inv;
    }
}

// ---------------- temporal transpose (b,t,s,c) <-> (b,s,t,c), c=512 ------------------
__global__ void transpose_kernel(const float* __restrict__ src, float* __restrict__ dst,
                                 int dir)
{
    int mIdx = blockIdx.x;
    int b = mIdx / (16 * 576);
    int r = mIdx % (16 * 576);
    int t = r / 576, s = r % 576;
    size_t ia = ((size_t)(b * 16 + t) * 576 + s) * DIMC;
    size_t ib = ((size_t)(b * 576 + s) * 16 + t) * DIMC;
    const float4* in;
    float4* out;
    if (dir == 0) { in = (const float4*)(src + ia); out = (float4*)(dst + ib); }
    else          { in = (const float4*)(src + ib); out = (float4*)(dst + ia); }
    out[threadIdx.x] = in[threadIdx.x];
}

// ---------------- GEGLU: out = u * gelu_exact(gate), out row stride FFIP -------------
__global__ void geglu_kernel(const float* __restrict__ ff, float* __restrict__ out)
{
    int m = blockIdx.x;
    const float* r = ff + (size_t)m * FF2I;
    float* o = out + (size_t)m * FFIP;
    for (int c = threadIdx.x; c < FFI; c += 256) {
        float u = r[c], g = r[FFI + c];
        o[c] = u * g * normcdff(g);
    }
}

// ---------------- host orchestration -------------------------------------------------
extern "C" void kernel_launch(void* const* d_in, const int* in_sizes, int n_in,
                              void* d_out, int out_size)
{
    (void)in_sizes; (void)n_in; (void)out_size;
    const float* x      = (const float*)d_in[0];
    const float* ctx    = (const float*)d_in[1];
    const float* sp_g   = (const float*)d_in[2];
    const float* sp_wq  = (const float*)d_in[3];
    const float* sp_wkv = (const float*)d_in[4];
    const float* sp_qs  = (const float*)d_in[5];
    const float* sp_ks  = (const float*)d_in[6];
    const float* sp_wo  = (const float*)d_in[7];
    const float* ca_g   = (const float*)d_in[8];
    const float* ca_cg  = (const float*)d_in[9];
    const float* ca_wq  = (const float*)d_in[10];
    const float* ca_wkv = (const float*)d_in[11];
    const float* ca_qs  = (const float*)d_in[12];
    const float* ca_ks  = (const float*)d_in[13];
    const float* ca_wo  = (const float*)d_in[14];
    const float* ca_nul = (const float*)d_in[15];
    const float* tp_g   = (const float*)d_in[16];
    const float* tp_wq  = (const float*)d_in[17];
    const float* tp_wkv = (const float*)d_in[18];
    const float* tp_qs  = (const float*)d_in[19];
    const float* tp_ks  = (const float*)d_in[20];
    const float* tp_wo  = (const float*)d_in[21];
    const float* ff_g   = (const float*)d_in[22];
    const float* ff_b   = (const float*)d_in[23];
    const float* ff_w1  = (const float*)d_in[24];
    const float* ff_w2  = (const float*)d_in[25];
    const float* out_g  = (const float*)d_in[26];
    float* out = (float*)d_out;

    float *px, *pln, *pq, *pk, *pv, *pqt, *pxt, *pkv, *pff;
    cudaGetSymbolAddress((void**)&px,  g_x);
    cudaGetSymbolAddress((void**)&pln, g_ln);
    cudaGetSymbolAddress((void**)&pq,  g_q);
    cudaGetSymbolAddress((void**)&pk,  g_k);
    cudaGetSymbolAddress((void**)&pv,  g_v);
    cudaGetSymbolAddress((void**)&pqt, g_qt);
    cudaGetSymbolAddress((void**)&pxt, g_xt);
    cudaGetSymbolAddress((void**)&pkv, g_kv);
    cudaGetSymbolAddress((void**)&pff, g_ff);

    dim3 bwh(32, 8);

    // ---- Phase A: spatial self-attention ----
    ln_kernel<<<TOK, 128>>>(x, sp_g, nullptr, pln);
    sgemm_tf32<<<dim3(4, 144), 256>>>(pln, 512, sp_wq, 512,  nullptr, pqt, TOK, 512, 512);
    sgemm_tf32<<<dim3(8, 144), 256>>>(pln, 512, sp_wkv, 1024, nullptr, pkv, TOK, 1024, 512);
    pack_kernel<<<TOK, bwh>>>(pqt, 512, 0,    pq, sp_qs,   8.0f, 576, 576, 0);
    pack_kernel<<<TOK, bwh>>>(pkv, 1024, 0,   pk, sp_ks,   1.0f, 576, 576, 0);
    pack_kernel<<<TOK, bwh>>>(pkv, 1024, 512, pv, nullptr, 1.0f, 576, 576, 0);
    attn_mma_kernel<<<dim3(9, 256), 128>>>(pq, pk, pv, pln, 576, 576);
    sgemm_tf32<<<dim3(4, 144), 256>>>(pln, 512, sp_wo, 512, x, px, TOK, 512, 512);

    // ---- Phase B: spatial cross-attention (null kv) ----
    ln_kernel<<<TOK, 128>>>(px, ca_g, nullptr, pln);
    ln_kernel<<<CTXTOK, 128>>>(ctx, ca_cg, nullptr, pxt);
    sgemm_tf32<<<dim3(4, 144), 256>>>(pln, 512, ca_wq, 512,  nullptr, pqt, TOK, 512, 512);
    sgemm_tf32<<<dim3(8, 20),  256>>>(pxt, 512, ca_wkv, 1024, nullptr, pkv, CTXTOK, 1024, 512);
    nullkv_kernel<<<32, bwh>>>(ca_nul, ca_ks, pk, pv, 79);
    pack_kernel<<<TOK, bwh>>>(pqt, 512, 0,       pq, ca_qs,   8.0f, 576, 576, 0);
    pack_kernel<<<CTXTOK, bwh>>>(pkv, 1024, 0,   pk, ca_ks,   1.0f, 77, 79, 2);
    pack_kernel<<<CTXTOK, bwh>>>(pkv, 1024, 512, pv, nullptr, 1.0f, 77, 79, 2);
    attn_mma_kernel<<<dim3(9, 256), 128>>>(pq, pk, pv, pln, 576, 79);
    sgemm_tf32<<<dim3(4, 144), 256>>>(pln, 512, ca_wo, 512, px, px, TOK, 512, 512);

    // ---- Phase C: temporal causal self-attention with ALiBi ----
    transpose_kernel<<<TOK, 128>>>(px, pxt, 0);
    ln_kernel<<<TOK, 128>>>(pxt, tp_g, nullptr, pln);
    sgemm_tf32<<<dim3(4, 144), 256>>>(pln, 512, tp_wq, 512,  nullptr, pqt, TOK, 512, 512);
    sgemm_tf32<<<dim3(8, 144), 256>>>(pln, 512, tp_wkv, 1024, nullptr, pkv, TOK, 1024, 512);
    pack_kernel<<<TOK, bwh>>>(pqt, 512, 0,    pq, tp_qs,   8.0f, 16, 16, 0);
    pack_kernel<<<TOK, bwh>>>(pkv, 1024, 0,   pk, tp_ks,   1.0f, 16, 16, 0);
    pack_kernel<<<TOK, bwh>>>(pkv, 1024, 512, pv, nullptr, 1.0f, 16, 16, 0);
    attn_kernel<<<dim3(2, 9216), 256>>>(pq, pk, pv, pln, 16, 16, 1);
    sgemm_tf32<<<dim3(4, 144), 256>>>(pln, 512, tp_wo, 512, pxt, pxt, TOK, 512, 512);
    transpose_kernel<<<TOK, 128>>>(pxt, px, 1);

    // ---- Phase D: GEGLU FF + final LN ----
    ln_kernel<<<TOK, 128>>>(px, ff_g, ff_b, pln);
    sgemm_tf32<<<dim3(22, 144), 256>>>(pln, 512, ff_w1, FF2I, nullptr, pff, TOK, FF2I, 512);
    geglu_kernel<<<TOK, 256>>>(pff, pkv);
    sgemm_tf32<<<dim3(4, 144), 256>>>(pkv, FFIP, ff_w2, 512, px, px, TOK, 512, FFI);
    ln_kernel<<<TOK, 128>>>(px, out_g, nullptr, out);
}

// round 6
// speedup vs baseline: 3.9548x; 1.6411x over previous
#include <cuda_runtime.h>
#include <cuda_bf16.h>
#include <math.h>
#include <stdint.h>

// ---------------- problem constants ----------------
#define TOK     18432          // 32 * 576 tokens (b*t, h*w)
#define CTXTOK  2464           // 32 * 77 context tokens
#define DIMC    512
#define NHEAD   8
#define DH      64
#define FFI     1365           // FF inner
#define FF1N    2732           // padded FF1 output columns (2*FFI -> /4)
#define FFIP    1376           // FF inner padded to /16 (FF2 K dimension)

// ---------------- scratch (device globals; no allocs allowed) ----------------
__device__ float g_x  [TOK * DIMC];
__device__ float g_ln [TOK * DIMC];
__device__ float g_q  [TOK * DIMC];
__device__ float g_k  [TOK * DIMC];
__device__ float g_v  [TOK * DIMC];
__device__ float g_qt [TOK * DIMC];
__device__ float g_xt [TOK * DIMC];
__device__ float g_kv [TOK * FFIP];
__device__ float g_ff [(size_t)TOK * FF1N];
__device__ float g_w1p[512 * FF1N];          // zero-padded ff_w1
__device__ float g_w2p[FFIP * 512];          // zero-padded ff_w2

// ---------------- LayerNorm over last dim (512), 128 threads/row ----------------
__global__ void ln_kernel(const float* __restrict__ x, const float* __restrict__ g,
                          const float* __restrict__ beta, float* __restrict__ y)
{
    __shared__ float sh[8];
    size_t row = blockIdx.x;
    float4 v = reinterpret_cast<const float4*>(x + row * DIMC)[threadIdx.x];
    float s = v.x + v.y + v.z + v.w;
    #pragma unroll
    for (int o = 16; o; o >>= 1) s += __shfl_xor_sync(0xffffffffu, s, o);
    if ((threadIdx.x & 31) == 0) sh[threadIdx.x >> 5] = s;
    __syncthreads();
    float mu = (sh[0] + sh[1] + sh[2] + sh[3]) * (1.0f / 512.0f);
    float dx = v.x - mu, dy = v.y - mu, dz = v.z - mu, dw = v.w - mu;
    float ss = dx * dx + dy * dy + dz * dz + dw * dw;
    #pragma unroll
    for (int o = 16; o; o >>= 1) ss += __shfl_xor_sync(0xffffffffu, ss, o);
    if ((threadIdx.x & 31) == 0) sh[4 + (threadIdx.x >> 5)] = ss;
    __syncthreads();
    float var = (sh[4] + sh[5] + sh[6] + sh[7]) * (1.0f / 512.0f);
    float inv = rsqrtf(var + 1e-5f);
    float4 gg = reinterpret_cast<const float4*>(g)[threadIdx.x];
    float4 o4;
    o4.x = dx * inv * gg.x;
    o4.y = dy * inv * gg.y;
    o4.z = dz * inv * gg.z;
    o4.w = dw * inv * gg.w;
    if (beta) {
        float4 bb = reinterpret_cast<const float4*>(beta)[threadIdx.x];
        o4.x += bb.x; o4.y += bb.y; o4.z += bb.z; o4.w += bb.w;
    }
    reinterpret_cast<float4*>(y + row * DIMC)[threadIdx.x] = o4;
}

// ---------------- mma helpers ----------------
__device__ __forceinline__ uint32_t cvt_tf32(float x)
{
    uint32_t r;
    asm("cvt.rna.tf32.f32 %0, %1;" : "=r"(r) : "f"(x));
    return r;
}

__device__ __forceinline__ void mma_tf32(float* c, const uint32_t* a, const uint32_t* b)
{
    asm volatile(
        "mma.sync.aligned.m16n8k8.row.col.f32.tf32.tf32.f32 "
        "{%0,%1,%2,%3}, {%4,%5,%6,%7}, {%8,%9}, {%0,%1,%2,%3};"
        : "+f"(c[0]), "+f"(c[1]), "+f"(c[2]), "+f"(c[3])
        : "r"(a[0]), "r"(a[1]), "r"(a[2]), "r"(a[3]), "r"(b[0]), "r"(b[1]));
}

__device__ __forceinline__ void mma_bf16(float* c, const uint32_t* a, uint32_t b0, uint32_t b1)
{
    asm volatile(
        "mma.sync.aligned.m16n8k16.row.col.f32.bf16.bf16.f32 "
        "{%0,%1,%2,%3}, {%4,%5,%6,%7}, {%8,%9}, {%0,%1,%2,%3};"
        : "+f"(c[0]), "+f"(c[1]), "+f"(c[2]), "+f"(c[3])
        : "r"(a[0]), "r"(a[1]), "r"(a[2]), "r"(a[3]), "r"(b0), "r"(b1));
}

__device__ __forceinline__ uint32_t pack_bf16(float lo, float hi)
{
    uint32_t r;
    asm("cvt.rn.bf16x2.f32 %0, %1, %2;" : "=r"(r) : "f"(hi), "f"(lo));
    return r;
}

__device__ __forceinline__ void cp_async16(uint32_t dst, const void* src, bool valid)
{
    asm volatile("cp.async.cg.shared.global [%0], [%1], 16, %2;"
                 :: "r"(dst), "l"(src), "r"(valid ? 16 : 0));
}
#define CP_COMMIT() asm volatile("cp.async.commit_group;")
#define CP_WAIT1()  asm volatile("cp.async.wait_group 1;")

// ---------------- tensor-core GEMM: C[M,N] = A[M,K] @ B[K,N] (+R) ------------------
// 128x128x16 tile, 8 warps, m16n8k8.tf32 (raw fp32 bits -> HW truncation).
// cp.async 3-stage pipeline, one barrier per k-step. Requires: 16B-aligned A/B rows
// (lda, ldb multiples of 4), K multiple of 16 with in-bounds rows (padded operands).
#define APITCH 20
#define BPITCH 136
#define GSTAGES 3
#define GEMM_SMEM ((GSTAGES * 128 * APITCH + GSTAGES * 16 * BPITCH) * 4)
__global__ __launch_bounds__(256, 2) void sgemm_tf32(const float* __restrict__ A, int lda,
                                                     const float* __restrict__ B, int ldb,
                                                     const float* __restrict__ R,
                                                     float* __restrict__ C,
                                                     int M, int N, int K)
{
    extern __shared__ float smem[];
    float* Asm = smem;                              // GSTAGES * 128 * APITCH
    float* Bsm = smem + GSTAGES * 128 * APITCH;     // GSTAGES * 16 * BPITCH
    int tid = threadIdx.x;
    int lane = tid & 31;
    int warp = tid >> 5;
    int wm = (warp >> 2) * 64;
    int wn = (warp & 3) * 32;
    int gl = lane >> 2, ql = lane & 3;
    int bm = blockIdx.y * 128, bn = blockIdx.x * 128;

    float acc[4][4][4];
    #pragma unroll
    for (int i = 0; i < 4; i++)
        #pragma unroll
        for (int j = 0; j < 4; j++)
            #pragma unroll
            for (int r = 0; r < 4; r++) acc[i][j][r] = 0.0f;

    auto stage = [&](int kb, int s) {
        float* as = Asm + s * 128 * APITCH;
        float* bs = Bsm + s * 16 * BPITCH;
        #pragma unroll
        for (int i = 0; i < 2; i++) {
            int gidx = tid + 256 * i;
            int m = gidx >> 2, k4 = (gidx & 3) * 4;
            const float* src = A + (size_t)(bm + m) * lda + kb + k4;
            cp_async16((uint32_t)__cvta_generic_to_shared(as + m * APITCH + k4),
                       src, (bm + m) < M);
        }
        #pragma unroll
        for (int i = 0; i < 2; i++) {
            int gidx = tid + 256 * i;
            int k = gidx >> 5, n4 = (gidx & 31) * 4;
            const float* src = B + (size_t)(kb + k) * ldb + bn + n4;
            cp_async16((uint32_t)__cvta_generic_to_shared(bs + k * BPITCH + n4),
                       src, (bn + n4) < N);
        }
    };

    auto compute = [&](int s) {
        const uint32_t* as = (const uint32_t*)(Asm + s * 128 * APITCH);
        const uint32_t* bs = (const uint32_t*)(Bsm + s * 16 * BPITCH);
        #pragma unroll
        for (int kt = 0; kt < 2; kt++) {
            int k0 = kt * 8;
            uint32_t a[4][4], b[4][2];
            #pragma unroll
            for (int mt = 0; mt < 4; mt++) {
                int m0 = wm + mt * 16 + gl;
                a[mt][0] = as[m0 * APITCH + k0 + ql];
                a[mt][1] = as[(m0 + 8) * APITCH + k0 + ql];
                a[mt][2] = as[m0 * APITCH + k0 + ql + 4];
                a[mt][3] = as[(m0 + 8) * APITCH + k0 + ql + 4];
            }
            #pragma unroll
            for (int nt = 0; nt < 4; nt++) {
                int n0 = wn + nt * 8 + gl;
                b[nt][0] = bs[(k0 + ql) * BPITCH + n0];
                b[nt][1] = bs[(k0 + 4 + ql) * BPITCH + n0];
            }
            #pragma unroll
            for (int mt = 0; mt < 4; mt++)
                #pragma unroll
                for (int nt = 0; nt < 4; nt++)
                    mma_tf32(acc[mt][nt], a[mt], b[nt]);
        }
    };

    int nk = K >> 4;
    stage(0, 0);  CP_COMMIT();
    stage(16, 1); CP_COMMIT();
    int s = 0;
    for (int it = 0; it < nk; it++) {
        CP_WAIT1();
        __syncthreads();
        compute(s);
        int nxt = it + 2;
        if (nxt < nk) stage(nxt << 4, (s + 2) % GSTAGES);
        CP_COMMIT();                 // empty group near the tail keeps counts aligned
        s = (s + 1) % GSTAGES;
    }

    #pragma unroll
    for (int mt = 0; mt < 4; mt++) {
        int r0 = bm + wm + mt * 16 + gl;
        #pragma unroll
        for (int nt = 0; nt < 4; nt++) {
            int c0 = bn + wn + nt * 8 + ql * 2;
            #pragma unroll
            for (int h = 0; h < 2; h++) {
                int rr = r0 + h * 8;
                if (rr >= M) continue;
                #pragma unroll
                for (int j = 0; j < 2; j++) {
                    int cc = c0 + j;
                    if (cc >= N) continue;
                    size_t idx = (size_t)rr * N + cc;
                    float val = acc[mt][nt][h * 2 + j];
                    if (R) val += R[idx];
                    C[idx] = val;
                }
            }
        }
    }
}

// ---------------- weight padding (once per launch; cheap) ---------------------------
__global__ void pad_w1_kernel(const float* __restrict__ w1, float* __restrict__ dst)
{
    int r = blockIdx.x;
    for (int c = threadIdx.x; c < FF1N; c += 256)
        dst[(size_t)r * FF1N + c] = (c < 2 * FFI) ? w1[(size_t)r * (2 * FFI) + c] : 0.0f;
}
__global__ void pad_w2_kernel(const float* __restrict__ w2, float* __restrict__ dst)
{
    int r = blockIdx.x;
    float4 v = make_float4(0.f, 0.f, 0.f, 0.f);
    if (r < FFI) v = reinterpret_cast<const float4*>(w2 + (size_t)r * 512)[threadIdx.x];
    reinterpret_cast<float4*>(dst + (size_t)r * 512)[threadIdx.x] = v;
}

// ---------------- tensor-core flash attention (non-causal) --------------------------
#define KPITCH 68     // floats per key row in smem (conflict-free b-frags)
#define VPITCH 40     // bf16 per d row in smem (conflict-free b-frags)
__global__ __launch_bounds__(128) void attn_mma_kernel(const float* __restrict__ Q,
                                                       const float* __restrict__ K,
                                                       const float* __restrict__ V,
                                                       float* __restrict__ O,
                                                       int NQ, int NK)
{
    __shared__ __align__(16) uint32_t Ks[32 * KPITCH];
    __shared__ __align__(16) __nv_bfloat16 Vst[64 * VPITCH];
    int tid = threadIdx.x;
    int lane = tid & 31, warp = tid >> 5;
    int gl = lane >> 2, ql = lane & 3;
    int bh = blockIdx.y;
    int q0 = blockIdx.x * 64 + warp * 16;

    uint32_t qf[8][4];
    const float* Qb = Q + ((size_t)bh * NQ + q0) * 64;
    #pragma unroll
    for (int kc = 0; kc < 8; kc++) {
        qf[kc][0] = cvt_tf32(Qb[gl * 64 + kc * 8 + ql]);
        qf[kc][1] = cvt_tf32(Qb[(gl + 8) * 64 + kc * 8 + ql]);
        qf[kc][2] = cvt_tf32(Qb[gl * 64 + kc * 8 + ql + 4]);
        qf[kc][3] = cvt_tf32(Qb[(gl + 8) * 64 + kc * 8 + ql + 4]);
    }

    float o[8][4];
    #pragma unroll
    for (int i = 0; i < 8; i++)
        #pragma unroll
        for (int j = 0; j < 4; j++) o[i][j] = 0.0f;
    float m0 = -1e30f, m1 = -1e30f, l0 = 0.0f, l1 = 0.0f;

    for (int kt = 0; kt < NK; kt += 32) {
        #pragma unroll
        for (int i = 0; i < 4; i++) {
            int f = tid + i * 128;
            int key = f >> 4;
            int c4 = f & 15;
            int jg = kt + key;
            float4 v = make_float4(0.f, 0.f, 0.f, 0.f);
            if (jg < NK) v = *(const float4*)(K + ((size_t)bh * NK + jg) * 64 + c4 * 4);
            uint4 w = make_uint4(cvt_tf32(v.x), cvt_tf32(v.y), cvt_tf32(v.z), cvt_tf32(v.w));
            *(uint4*)&Ks[key * KPITCH + c4 * 4] = w;
        }
        {
            int key = tid & 31, dg = tid >> 5;
            int jg = kt + key;
            #pragma unroll
            for (int i = 0; i < 4; i++) {
                int d0 = dg * 16 + i * 4;
                float4 v = make_float4(0.f, 0.f, 0.f, 0.f);
                if (jg < NK) v = *(const float4*)(V + ((size_t)bh * NK + jg) * 64 + d0);
                Vst[(d0 + 0) * VPITCH + key] = __float2bfloat16(v.x);
                Vst[(d0 + 1) * VPITCH + key] = __float2bfloat16(v.y);
                Vst[(d0 + 2) * VPITCH + key] = __float2bfloat16(v.z);
                Vst[(d0 + 3) * VPITCH + key] = __float2bfloat16(v.w);
            }
        }
        __syncthreads();

        float s[4][4];
        #pragma unroll
        for (int nt = 0; nt < 4; nt++)
            #pragma unroll
            for (int j = 0; j < 4; j++) s[nt][j] = 0.0f;
        #pragma unroll
        for (int kc = 0; kc < 8; kc++) {
            #pragma unroll
            for (int nt = 0; nt < 4; nt++) {
                uint32_t b[2];
                b[0] = Ks[(nt * 8 + gl) * KPITCH + kc * 8 + ql];
                b[1] = Ks[(nt * 8 + gl) * KPITCH + kc * 8 + ql + 4];
                mma_tf32(s[nt], qf[kc], b);
            }
        }

        if (kt + 32 > NK) {
            #pragma unroll
            for (int nt = 0; nt < 4; nt++) {
                int jg = kt + nt * 8 + 2 * ql;
                if (jg >= NK)     { s[nt][0] = -1e30f; s[nt][2] = -1e30f; }
                if (jg + 1 >= NK) { s[nt][1] = -1e30f; s[nt][3] = -1e30f; }
            }
        }

        float tm0 = -1e30f, tm1 = -1e30f;
        #pragma unroll
        for (int nt = 0; nt < 4; nt++) {
            tm0 = fmaxf(tm0, fmaxf(s[nt][0], s[nt][1]));
            tm1 = fmaxf(tm1, fmaxf(s[nt][2], s[nt][3]));
        }
        #pragma unroll
        for (int off = 1; off <= 2; off <<= 1) {
            tm0 = fmaxf(tm0, __shfl_xor_sync(0xffffffffu, tm0, off));
            tm1 = fmaxf(tm1, __shfl_xor_sync(0xffffffffu, tm1, off));
        }
        float nm0 = fmaxf(m0, tm0), nm1 = fmaxf(m1, tm1);
        float c0 = __expf(m0 - nm0), c1 = __expf(m1 - nm1);
        float rs0 = 0.0f, rs1 = 0.0f;
        #pragma unroll
        for (int nt = 0; nt < 4; nt++) {
            s[nt][0] = __expf(s[nt][0] - nm0);
            s[nt][1] = __expf(s[nt][1] - nm0);
            s[nt][2] = __expf(s[nt][2] - nm1);
            s[nt][3] = __expf(s[nt][3] - nm1);
            rs0 += s[nt][0] + s[nt][1];
            rs1 += s[nt][2] + s[nt][3];
        }
        #pragma unroll
        for (int off = 1; off <= 2; off <<= 1) {
            rs0 += __shfl_xor_sync(0xffffffffu, rs0, off);
            rs1 += __shfl_xor_sync(0xffffffffu, rs1, off);
        }
        l0 = l0 * c0 + rs0;
        l1 = l1 * c1 + rs1;
        m0 = nm0; m1 = nm1;
        #pragma unroll
        for (int nt = 0; nt < 8; nt++) {
            o[nt][0] *= c0; o[nt][1] *= c0;
            o[nt][2] *= c1; o[nt][3] *= c1;
        }

        #pragma unroll
        for (int kc = 0; kc < 2; kc++) {
            uint32_t a[4];
            a[0] = pack_bf16(s[2 * kc][0],     s[2 * kc][1]);
            a[1] = pack_bf16(s[2 * kc][2],     s[2 * kc][3]);
            a[2] = pack_bf16(s[2 * kc + 1][0], s[2 * kc + 1][1]);
            a[3] = pack_bf16(s[2 * kc + 1][2], s[2 * kc + 1][3]);
            #pragma unroll
            for (int nt = 0; nt < 8; nt++) {
                const __nv_bfloat16* vp = &Vst[(nt * 8 + gl) * VPITCH + kc * 16 + 2 * ql];
                uint32_t b0 = *(const uint32_t*)vp;
                uint32_t b1 = *(const uint32_t*)(vp + 8);
                mma_bf16(o[nt], a, b0, b1);
            }
        }
        __syncthreads();
    }

    float inv0 = 1.0f / l0, inv1 = 1.0f / l1;
    int b = bh >> 3, h = bh & 7;
    #pragma unroll
    for (int nt = 0; nt < 8; nt++) {
        int d = h * 64 + nt * 8 + 2 * ql;
        float2 v0 = make_float2(o[nt][0] * inv0, o[nt][1] * inv0);
        float2 v1 = make_float2(o[nt][2] * inv1, o[nt][3] * inv1);
        *(float2*)&O[((size_t)b * NQ + q0 + gl) * DIMC + d] = v0;
        *(float2*)&O[((size_t)b * NQ + q0 + gl + 8) * DIMC + d] = v1;
    }
}

// ---------------- pack token-major -> [BH, N, 64] with optional l2norm*scale*mult ----
__global__ void pack_kernel(const float* __restrict__ src, int stride, int off,
                            float* __restrict__ dst, const float* __restrict__ scale,
                            float mult, int srcN, int dstN, int dstPos)
{
    int m = blockIdx.x;
    int h = threadIdx.y, lane = threadIdx.x;
    int b = m / srcN, i = m % srcN;
    size_t s = (size_t)m * stride + off + h * 64;
    float x0 = src[s + lane], x1 = src[s + 32 + lane];
    float f0 = mult, f1 = mult;
    if (scale) {
        float ss = x0 * x0 + x1 * x1;
        #pragma unroll
        for (int o = 16; o; o >>= 1) ss += __shfl_xor_sync(0xffffffffu, ss, o);
        float inv = 1.0f / fmaxf(sqrtf(ss), 1e-12f);
        f0 = inv * scale[lane] * mult;
        f1 = inv * scale[lane + 32] * mult;
    }
    size_t d = ((size_t)(b * NHEAD + h) * dstN + dstPos + i) * 64;
    dst[d + lane]      = x0 * f0;
    dst[d + 32 + lane] = x1 * f1;
}

// ---------------- fill null-KV tokens (cross-attn) ----------------------------------
__global__ void nullkv_kernel(const float* __restrict__ nkv, const float* __restrict__ ks,
                              float* __restrict__ Kd, float* __restrict__ Vd, int NK)
{
    int b = blockIdx.x; int h = threadIdx.y; int lane = threadIdx.x;
    for (int p = 0; p < 2; p++) {
        const float* nk = nkv + ((size_t)h * 4 + 2 * p) * 64;
        const float* nv = nk + 64;
        float k0 = nk[lane], k1 = nk[lane + 32];
        float ss = k0 * k0 + k1 * k1;
        #pragma unroll
        for (int o = 16; o; o >>= 1) ss += __shfl_xor_sync(0xffffffffu, ss, o);
        float inv = 1.0f / fmaxf(sqrtf(ss), 1e-12f);
        size_t base = ((size_t)(b * NHEAD + h) * NK + p) * 64;
        Kd[base + lane]      = k0 * inv * ks[lane];
        Kd[base + 32 + lane] = k1 * inv * ks[lane + 32];
        Vd[base + lane]      = nv[lane];
        Vd[base + 32 + lane] = nv[lane + 32];
    }
}

// ---------------- scalar attention (temporal: NK=16, causal + ALiBi) ----------------
__global__ __launch_bounds__(256) void attn_kernel(const float* __restrict__ Q,
                                                   const float* __restrict__ K,
                                                   const float* __restrict__ V,
                                                   float* __restrict__ O,
                                                   int NQ, int NK, int causal)
{
    __shared__ float Ks[32][64];
    __shared__ float Vs[32][64];
    int bh = blockIdx.y;
    int tid = threadIdx.x;
    int w = tid >> 5, lane = tid & 31;
    int qi = blockIdx.x * 8 + w;
    bool qv = qi < NQ;
    float qa = 0.f, qb = 0.f;
    if (qv) {
        size_t qoff = ((size_t)bh * NQ + qi) * 64;
        qa = Q[qoff + lane];
        qb = Q[qoff + 32 + lane];
    }
    float m = -1e30f, l = 0.f, acc0 = 0.f, acc1 = 0.f;
    float slope = exp2f(-(float)((bh & 7) + 1));

    for (int kt = 0; kt < NK; kt += 32) {
        for (int f = tid; f < 2048; f += 256) {
            int j = f >> 6, d = f & 63;
            int jg = kt + j;
            bool ok = jg < NK;
            size_t off = ((size_t)bh * NK + (ok ? jg : 0)) * 64 + d;
            Ks[j][d] = ok ? K[off] : 0.0f;
            Vs[j][d] = ok ? V[off] : 0.0f;
        }
        __syncthreads();
        if (qv) {
            int jmax = NK - kt; if (jmax > 32) jmax = 32;
            for (int j = 0; j < jmax; j++) {
                int jg = kt + j;
                if (causal && jg > qi) break;
                float s = qa * Ks[j][lane] + qb * Ks[j][lane + 32];
                #pragma unroll
                for (int o = 16; o; o >>= 1) s += __shfl_xor_sync(0xffffffffu, s, o);
                if (causal) s -= slope * (float)(qi - jg);
                float mn = fmaxf(m, s);
                float corr = __expf(m - mn);
                float p = __expf(s - mn);
                l    = l * corr + p;
                acc0 = acc0 * corr + p * Vs[j][lane];
                acc1 = acc1 * corr + p * Vs[j][lane + 32];
                m = mn;
            }
        }
        __syncthreads();
    }
    if (qv) {
        float inv = 1.0f / l;
        int b = bh >> 3, hh = bh & 7;
        size_t o = ((size_t)b * NQ + qi) * DIMC + hh * 64;
        O[o + lane]      = acc0 * inv;
        O[o + 32 + lane] = acc1 * inv;
    }
}

// ---------------- temporal transpose (b,t,s,c) <-> (b,s,t,c), c=512 ------------------
__global__ void transpose_kernel(const float* __restrict__ src, float* __restrict__ dst,
                                 int dir)
{
    int mIdx = blockIdx.x;
    int b = mIdx / (16 * 576);
    int r = mIdx % (16 * 576);
    int t = r / 576, s = r % 576;
    size_t ia = ((size_t)(b * 16 + t) * 576 + s) * DIMC;
    size_t ib = ((size_t)(b * 576 + s) * 16 + t) * DIMC;
    const float4* in;
    float4* out;
    if (dir == 0) { in = (const float4*)(src + ia); out = (float4*)(dst + ib); }
    else          { in = (const float4*)(src + ib); out = (float4*)(dst + ia); }
    out[threadIdx.x] = in[threadIdx.x];
}

// ---------------- GEGLU: out = u * gelu_exact(gate); zero-pads cols FFI..FFIP -------
__global__ void geglu_kernel(const float* __restrict__ ff, float* __restrict__ out)
{
    int m = blockIdx.x;
    const float* r = ff + (size_t)m * FF1N;
    float* o = out + (size_t)m * FFIP;
    for (int c = threadIdx.x; c < FFIP; c += 256) {
        float val = 0.0f;
        if (c < FFI) {
            float u = r[c], g = r[FFI + c];
            val = u * g * normcdff(g);
        }
        o[c] = val;
    }
}

// ---------------- host orchestration -------------------------------------------------
extern "C" void kernel_launch(void* const* d_in, const int* in_sizes, int n_in,
                              void* d_out, int out_size)
{
    (void)in_sizes; (void)n_in; (void)out_size;
    const float* x      = (const float*)d_in[0];
    const float* ctx    = (const float*)d_in[1];
    const float* sp_g   = (const float*)d_in[2];
    const float* sp_wq  = (const float*)d_in[3];
    const float* sp_wkv = (const float*)d_in[4];
    const float* sp_qs  = (const float*)d_in[5];
    const float* sp_ks  = (const float*)d_in[6];
    const float* sp_wo  = (const float*)d_in[7];
    const float* ca_g   = (const float*)d_in[8];
    const float* ca_cg  = (const float*)d_in[9];
    const float* ca_wq  = (const float*)d_in[10];
    const float* ca_wkv = (const float*)d_in[11];
    const float* ca_qs  = (const float*)d_in[12];
    const float* ca_ks  = (const float*)d_in[13];
    const float* ca_wo  = (const float*)d_in[14];
    const float* ca_nul = (const float*)d_in[15];
    const float* tp_g   = (const float*)d_in[16];
    const float* tp_wq  = (const float*)d_in[17];
    const float* tp_wkv = (const float*)d_in[18];
    const float* tp_qs  = (const float*)d_in[19];
    const float* tp_ks  = (const float*)d_in[20];
    const float* tp_wo  = (const float*)d_in[21];
    const float* ff_g   = (const float*)d_in[22];
    const float* ff_b   = (const float*)d_in[23];
    const float* ff_w1  = (const float*)d_in[24];
    const float* ff_w2  = (const float*)d_in[25];
    const float* out_g  = (const float*)d_in[26];
    float* out = (float*)d_out;

    float *px, *pln, *pq, *pk, *pv, *pqt, *pxt, *pkv, *pff, *pw1, *pw2;
    cudaGetSymbolAddress((void**)&px,  g_x);
    cudaGetSymbolAddress((void**)&pln, g_ln);
    cudaGetSymbolAddress((void**)&pq,  g_q);
    cudaGetSymbolAddress((void**)&pk,  g_k);
    cudaGetSymbolAddress((void**)&pv,  g_v);
    cudaGetSymbolAddress((void**)&pqt, g_qt);
    cudaGetSymbolAddress((void**)&pxt, g_xt);
    cudaGetSymbolAddress((void**)&pkv, g_kv);
    cudaGetSymbolAddress((void**)&pff, g_ff);
    cudaGetSymbolAddress((void**)&pw1, g_w1p);
    cudaGetSymbolAddress((void**)&pw2, g_w2p);

    static bool attr_set = false;
    if (!attr_set) {
        cudaFuncSetAttribute(sgemm_tf32, cudaFuncAttributeMaxDynamicSharedMemorySize,
                             GEMM_SMEM);
        attr_set = true;
    }

    dim3 bwh(32, 8);

    // ---- weight padding (independent of activations) ----
    pad_w1_kernel<<<512, 256>>>(ff_w1, pw1);
    pad_w2_kernel<<<FFIP, 128>>>(ff_w2, pw2);

    // ---- Phase A: spatial self-attention ----
    ln_kernel<<<TOK, 128>>>(x, sp_g, nullptr, pln);
    sgemm_tf32<<<dim3(4, 144), 256, GEMM_SMEM>>>(pln, 512, sp_wq, 512,  nullptr, pqt, TOK, 512, 512);
    sgemm_tf32<<<dim3(8, 144), 256, GEMM_SMEM>>>(pln, 512, sp_wkv, 1024, nullptr, pkv, TOK, 1024, 512);
    pack_kernel<<<TOK, bwh>>>(pqt, 512, 0,    pq, sp_qs,   8.0f, 576, 576, 0);
    pack_kernel<<<TOK, bwh>>>(pkv, 1024, 0,   pk, sp_ks,   1.0f, 576, 576, 0);
    pack_kernel<<<TOK, bwh>>>(pkv, 1024, 512, pv, nullptr, 1.0f, 576, 576, 0);
    attn_mma_kernel<<<dim3(9, 256), 128>>>(pq, pk, pv, pln, 576, 576);
    sgemm_tf32<<<dim3(4, 144), 256, GEMM_SMEM>>>(pln, 512, sp_wo, 512, x, px, TOK, 512, 512);

    // ---- Phase B: spatial cross-attention (null kv) ----
    ln_kernel<<<TOK, 128>>>(px, ca_g, nullptr, pln);
    ln_kernel<<<CTXTOK, 128>>>(ctx, ca_cg, nullptr, pxt);
    sgemm_tf32<<<dim3(4, 144), 256, GEMM_SMEM>>>(pln, 512, ca_wq, 512,  nullptr, pqt, TOK, 512, 512);
    sgemm_tf32<<<dim3(8, 20),  256, GEMM_SMEM>>>(pxt, 512, ca_wkv, 1024, nullptr, pkv, CTXTOK, 1024, 512);
    nullkv_kernel<<<32, bwh>>>(ca_nul, ca_ks, pk, pv, 79);
    pack_kernel<<<TOK, bwh>>>(pqt, 512, 0,       pq, ca_qs,   8.0f, 576, 576, 0);
    pack_kernel<<<CTXTOK, bwh>>>(pkv, 1024, 0,   pk, ca_ks,   1.0f, 77, 79, 2);
    pack_kernel<<<CTXTOK, bwh>>>(pkv, 1024, 512, pv, nullptr, 1.0f, 77, 79, 2);
    attn_mma_kernel<<<dim3(9, 256), 128>>>(pq, pk, pv, pln, 576, 79);
    sgemm_tf32<<<dim3(4, 144), 256, GEMM_SMEM>>>(pln, 512, ca_wo, 512, px, px, TOK, 512, 512);

    // ---- Phase C: temporal causal self-attention with ALiBi ----
    transpose_kernel<<<TOK, 128>>>(px, pxt, 0);
    ln_kernel<<<TOK, 128>>>(pxt, tp_g, nullptr, pln);
    sgemm_tf32<<<dim3(4, 144), 256, GEMM_SMEM>>>(pln, 512, tp_wq, 512,  nullptr, pqt, TOK, 512, 512);
    sgemm_tf32<<<dim3(8, 144), 256, GEMM_SMEM>>>(pln, 512, tp_wkv, 1024, nullptr, pkv, TOK, 1024, 512);
    pack_kernel<<<TOK, bwh>>>(pqt, 512, 0,    pq, tp_qs,   8.0f, 16, 16, 0);
    pack_kernel<<<TOK, bwh>>>(pkv, 1024, 0,   pk, tp_ks,   1.0f, 16, 16, 0);
    pack_kernel<<<TOK, bwh>>>(pkv, 1024, 512, pv, nullptr, 1.0f, 16, 16, 0);
    attn_kernel<<<dim3(2, 9216), 256>>>(pq, pk, pv, pln, 16, 16, 1);
    sgemm_tf32<<<dim3(4, 144), 256, GEMM_SMEM>>>(pln, 512, tp_wo, 512, pxt, pxt, TOK, 512, 512);
    transpose_kernel<<<TOK, 128>>>(pxt, px, 1);

    // ---- Phase D: GEGLU FF + final LN ----
    ln_kernel<<<TOK, 128>>>(px, ff_g, ff_b, pln);
    sgemm_tf32<<<dim3(22, 144), 256, GEMM_SMEM>>>(pln, 512, pw1, FF1N, nullptr, pff, TOK, FF1N, 512);
    geglu_kernel<<<TOK, 256>>>(pff, pkv);
    sgemm_tf32<<<dim3(4, 144), 256, GEMM_SMEM>>>(pkv, FFIP, pw2, 512, px, px, TOK, 512, FFIP);
    ln_kernel<<<TOK, 128>>>(px, out_g, nullptr, out);
}